// round 4
// baseline (speedup 1.0000x reference)
#include <cuda_runtime.h>

// Problem constants
#define BATCH 8
#define IMH 180
#define IMW 180
#define NF 24
#define NB 31
#define NPIX (IMH * IMW)          // 32400
#define NTOT (BATCH * NPIX)       // 259200
#define N4   (NTOT / 4)           // 64800

#define TILE 32
#define UT 40                      // u tile (TILE + 2*4)
#define PT 36                      // phi tile (TILE + 2*2)

// LUT for phi(x) = sum_j w_j exp(-50 (x-mu_j)^2), x in [XMIN, XMAX]
#define NCELL 2048
#define XMIN (-2.0f)
#define XMAX (2.0f)
#define LUT_H ((XMAX - XMIN) / (float)NCELL)
#define LUT_INVH ((float)NCELL / (XMAX - XMIN))

#define NTHR 512                   // 2 filter-groups of 256 threads
#define NFG  12                    // filters per group

__device__ float  g_partials[64];
__device__ float2 g_lut[NCELL];

// ---------------------------------------------------------------------------
// k_init: blocks [0,8) build the 2048-cell LUT; blocks [8,72) compute weighted
// partial sums for M: sum(u_sigma)*9 = sum_p u[p]*cnt(p).
// ---------------------------------------------------------------------------
__global__ void k_init(const float* __restrict__ u,
                       const float* __restrict__ mu,
                       const float* __restrict__ wts) {
    const int tid = threadIdx.x;
    if (blockIdx.x < 8) {
        int i = blockIdx.x * 256 + tid;        // 0..2047
        float x0 = XMIN + (float)i * LUT_H;
        float x1 = x0 + LUT_H;
        float p0 = 0.f, p1 = 0.f;
        #pragma unroll 1
        for (int j = 0; j < NB; j++) {
            float m = mu[j], w = wts[j];
            float d0 = x0 - m, d1 = x1 - m;
            p0 += w * expf(-50.f * d0 * d0);
            p1 += w * expf(-50.f * d1 * d1);
        }
        g_lut[i] = make_float2(p0, p1 - p0);
    } else {
        __shared__ float sm[256];
        const int pb = blockIdx.x - 8;         // 0..63
        float s = 0.f;
        for (int i = pb * 256 + tid; i < N4; i += 64 * 256) {
            int idx4 = i * 4;
            int p = idx4 % NPIX;
            int y = p / IMW;
            int x0 = p - y * IMW;
            float wy = 3.f - (y == 0 ? 1.f : 0.f) - (y == IMH - 1 ? 1.f : 0.f);
            float4 v = ((const float4*)u)[i];
            float w0 = (x0 == 0) ? 2.f : 3.f;
            float w3 = (x0 == IMW - 4) ? 2.f : 3.f;
            s += wy * (v.x * w0 + v.y * 3.f + v.z * 3.f + v.w * w3);
        }
        sm[tid] = s;
        __syncthreads();
        for (int o = 128; o > 0; o >>= 1) {
            if (tid < o) sm[tid] += sm[tid + o];
            __syncthreads();
        }
        if (tid == 0) g_partials[pb] = sm[0];
    }
}

// ---------------------------------------------------------------------------
// k_main: fused TNRD stage per 32x32 tile; 2 filter-groups of 256 threads.
// Dynamic smem layout (bytes):
//   [0, 16384)         sLUT  : 2048 x float2
//   [16384, 22784)     sU    : 40x40
//   [22784, 27968)     sUS   : 36x36 (u_sigma/M, zeroed outside image)
//   [27968, 48704)     sPhi  : 4 buffers of 36x36 (group*2 + parity)
//   [48704, 51104)     sF    : 24x25
// ---------------------------------------------------------------------------
#define SMEM_BYTES 51104
#define OFF_LUT 0
#define OFF_U   16384
#define OFF_US  22784
#define OFF_PHI 27968
#define OFF_F   48704
#define PHI_STRIDE 5184

__global__ __launch_bounds__(NTHR, 2) void k_main(
    const float* __restrict__ u,
    const float* __restrict__ f,
    const float* __restrict__ filt,
    const float* __restrict__ lam,
    float* __restrict__ out)
{
    extern __shared__ char smem[];
    float2* sLUT = (float2*)(smem + OFF_LUT);
    float*  sU   = (float*)(smem + OFF_U);
    float*  sUS  = (float*)(smem + OFF_US);
    float*  sF   = (float*)(smem + OFF_F);
    __shared__ float red[64];

    const int b   = blockIdx.z;
    const int oy0 = blockIdx.y * TILE;
    const int ox0 = blockIdx.x * TILE;
    const int tid = threadIdx.x;
    const int g   = tid >> 8;          // filter-group 0/1
    const int gt  = tid & 255;         // lane within group

    const float* ub = u + b * NPIX;
    const float* fb = f + b * NPIX;
    float* ob = out + b * NPIX;

    // ---- cooperative loads ----
    if (tid < 64) red[tid] = g_partials[tid];
    {
        const float4* lg = (const float4*)g_lut;
        float4* ls = (float4*)sLUT;
        #pragma unroll
        for (int k = 0; k < (NCELL / 2) / NTHR; k++)   // 1024 float4
            ls[tid + k * NTHR] = lg[tid + k * NTHR];
    }
    for (int i = tid; i < NF * 25; i += NTHR) sF[i] = filt[i];
    for (int i = tid; i < UT * UT; i += NTHR) {
        int r = i / UT, c = i - r * UT;
        int gy = oy0 - 4 + r, gx = ox0 - 4 + c;
        float v = 0.f;
        if ((unsigned)gy < IMH && (unsigned)gx < IMW) v = ub[gy * IMW + gx];
        sU[i] = v;
    }
    __syncthreads();

    // ---- reduce partials -> invM (deterministic tree) ----
    for (int o = 32; o > 0; o >>= 1) {
        if (tid < o) red[tid] += red[tid + o];
        __syncthreads();
    }
    const float invM = 1.f / (red[0] / (9.f * (float)NTOT) + 0.001f);

    // ---- u_sigma/M on phi tile; zero outside image ----
    for (int i = tid; i < PT * PT; i += NTHR) {
        int r = i / PT, c = i - r * PT;
        int gy = oy0 - 2 + r, gx = ox0 - 2 + c;
        float v = 0.f;
        if ((unsigned)gy < IMH && (unsigned)gx < IMW) {
            float s0 = sU[(r + 1) * UT + c + 1] + sU[(r + 1) * UT + c + 2] + sU[(r + 1) * UT + c + 3];
            float s1 = sU[(r + 2) * UT + c + 1] + sU[(r + 2) * UT + c + 2] + sU[(r + 2) * UT + c + 3];
            float s2 = sU[(r + 3) * UT + c + 1] + sU[(r + 3) * UT + c + 2] + sU[(r + 3) * UT + c + 3];
            v = (s0 + s1 + s2) * (1.f / 9.f) * invM;
        }
        sUS[i] = v;
    }
    __syncthreads();

    // ---- per-group pipeline over NFG filters ----
    const int qy  = gt >> 3;               // 0..31
    const int qc0 = (gt & 7) * 4;          // 0..28
    float acc0 = 0.f, acc1 = 0.f, acc2 = 0.f, acc3 = 0.f;
    const int fbase = g * NFG;
    float* phiBuf[2] = { (float*)(smem + OFF_PHI + (2 * g + 0) * PHI_STRIDE),
                         (float*)(smem + OFF_PHI + (2 * g + 1) * PHI_STRIDE) };

    #define GBAR() asm volatile("bar.sync %0, %1;" :: "r"(g + 1), "r"(256) : "memory")

    #define FORWARD(DST, FARR)                                                \
        for (int t = gt; t < 324; t += 256) {                                 \
            int r = t / 9, c0 = (t - r * 9) * 4;                              \
            float s0 = 0.f, s1 = 0.f, s2 = 0.f, s3 = 0.f;                     \
            _Pragma("unroll")                                                 \
            for (int dy = 0; dy < 5; dy++) {                                  \
                const float4* row = (const float4*)&sU[(r + dy) * UT + c0];   \
                float4 A = row[0];                                            \
                float4 Bv = row[1];                                           \
                const float* Fr = &FARR[dy * 5];                              \
                s0 = fmaf(A.x, Fr[0], s0); s1 = fmaf(A.y, Fr[0], s1);         \
                s2 = fmaf(A.z, Fr[0], s2); s3 = fmaf(A.w, Fr[0], s3);         \
                s0 = fmaf(A.y, Fr[1], s0); s1 = fmaf(A.z, Fr[1], s1);         \
                s2 = fmaf(A.w, Fr[1], s2); s3 = fmaf(Bv.x, Fr[1], s3);        \
                s0 = fmaf(A.z, Fr[2], s0); s1 = fmaf(A.w, Fr[2], s1);         \
                s2 = fmaf(Bv.x, Fr[2], s2); s3 = fmaf(Bv.y, Fr[2], s3);       \
                s0 = fmaf(A.w, Fr[3], s0); s1 = fmaf(Bv.x, Fr[3], s1);        \
                s2 = fmaf(Bv.y, Fr[3], s2); s3 = fmaf(Bv.z, Fr[3], s3);       \
                s0 = fmaf(Bv.x, Fr[4], s0); s1 = fmaf(Bv.y, Fr[4], s1);       \
                s2 = fmaf(Bv.z, Fr[4], s2); s3 = fmaf(Bv.w, Fr[4], s3);       \
            }                                                                 \
            float conv[4] = {s0, s1, s2, s3};                                 \
            float4 usv = *(const float4*)&sUS[r * PT + c0];                   \
            float usa[4] = {usv.x, usv.y, usv.z, usv.w};                      \
            float res[4];                                                     \
            _Pragma("unroll")                                                 \
            for (int k2 = 0; k2 < 4; k2++) {                                  \
                float xc = fminf(fmaxf(conv[k2], XMIN), XMAX);                \
                float tt = (xc - XMIN) * LUT_INVH;                            \
                int ii = (int)tt;                                             \
                ii = min(ii, NCELL - 1);                                      \
                float frac = tt - (float)ii;                                  \
                float2 cell = sLUT[ii];                                       \
                res[k2] = usa[k2] * fmaf(cell.y, frac, cell.x);               \
            }                                                                 \
            *(float4*)&DST[r * PT + c0] =                                     \
                make_float4(res[0], res[1], res[2], res[3]);                  \
        }

    #define ADJOINT(SRC, FI)                                                  \
        {                                                                     \
            float a0 = 0.f, a1 = 0.f, a2 = 0.f, a3 = 0.f;                     \
            const float* Fs = &sF[(FI) * 25];                                 \
            _Pragma("unroll")                                                 \
            for (int dy = 0; dy < 5; dy++) {                                  \
                const float4* row = (const float4*)&SRC[(qy + dy) * PT + qc0];\
                float4 A = row[0];                                            \
                float4 Bv = row[1];                                           \
                const float* Fr = &Fs[(4 - dy) * 5];                          \
                a0 = fmaf(A.x, Fr[4], a0); a1 = fmaf(A.y, Fr[4], a1);         \
                a2 = fmaf(A.z, Fr[4], a2); a3 = fmaf(A.w, Fr[4], a3);         \
                a0 = fmaf(A.y, Fr[3], a0); a1 = fmaf(A.z, Fr[3], a1);         \
                a2 = fmaf(A.w, Fr[3], a2); a3 = fmaf(Bv.x, Fr[3], a3);        \
                a0 = fmaf(A.z, Fr[2], a0); a1 = fmaf(A.w, Fr[2], a1);         \
                a2 = fmaf(Bv.x, Fr[2], a2); a3 = fmaf(Bv.y, Fr[2], a3);       \
                a0 = fmaf(A.w, Fr[1], a0); a1 = fmaf(Bv.x, Fr[1], a1);        \
                a2 = fmaf(Bv.y, Fr[1], a2); a3 = fmaf(Bv.z, Fr[1], a3);       \
                a0 = fmaf(Bv.x, Fr[0], a0); a1 = fmaf(Bv.y, Fr[0], a1);       \
                a2 = fmaf(Bv.z, Fr[0], a2); a3 = fmaf(Bv.w, Fr[0], a3);       \
            }                                                                 \
            acc0 += a0; acc1 += a1; acc2 += a2; acc3 += a3;                   \
        }

    float F[25];
    #pragma unroll
    for (int j = 0; j < 25; j++) F[j] = sF[fbase * 25 + j];
    FORWARD(phiBuf[0], F)
    GBAR();

    #pragma unroll 1
    for (int k = 0; k < NFG; k++) {
        const int nxt = k + 1;
        if (nxt < NFG) {
            #pragma unroll
            for (int j = 0; j < 25; j++) F[j] = sF[(fbase + nxt) * 25 + j];
            if (nxt & 1) { FORWARD(phiBuf[1], F) } else { FORWARD(phiBuf[0], F) }
        }
        if (k & 1) { ADJOINT(phiBuf[1], fbase + k) } else { ADJOINT(phiBuf[0], fbase + k) }
        GBAR();
    }
    #undef FORWARD
    #undef ADJOINT
    #undef GBAR

    // ---- combine group accumulators, epilogue ----
    float4* comb = (float4*)(smem + OFF_PHI);       // reuse group0 bufA
    if (g == 0) comb[gt] = make_float4(acc0, acc1, acc2, acc3);
    __syncthreads();
    if (g == 1) {
        float4 c = comb[gt];
        acc0 += c.x; acc1 += c.y; acc2 += c.z; acc3 += c.w;
        const float lambda = lam[0];
        const int gy = oy0 + qy;
        float accs[4] = {acc0, acc1, acc2, acc3};
        float4 uv4 = *(const float4*)&sU[(qy + 4) * UT + qc0 + 4];
        float uvs[4] = {uv4.x, uv4.y, uv4.z, uv4.w};
        if (gy < IMH) {
            #pragma unroll
            for (int k = 0; k < 4; k++) {
                int gx = ox0 + qc0 + k;
                if (gx < IMW) {
                    float uv = uvs[k];
                    float fv = fb[gy * IMW + gx];
                    float reac = lambda * (uv - fv) / (uv * uv + 1e-3f);
                    float o = uv - accs[k] - reac;
                    o = fminf(fmaxf(o, 0.f), 1.f);
                    ob[gy * IMW + gx] = o;
                }
            }
        }
    }
}

// ---------------------------------------------------------------------------
// Launch
// ---------------------------------------------------------------------------
extern "C" void kernel_launch(void* const* d_in, const int* in_sizes, int n_in,
                              void* d_out, int out_size) {
    const float* u    = (const float*)d_in[0];
    const float* f    = (const float*)d_in[1];
    const float* filt = (const float*)d_in[2];
    const float* lam  = (const float*)d_in[3];
    const float* mu   = (const float*)d_in[4];
    const float* wts  = (const float*)d_in[5];
    float* out = (float*)d_out;

    static bool attr_set = false;
    if (!attr_set) {
        cudaFuncSetAttribute(k_main, cudaFuncAttributeMaxDynamicSharedMemorySize,
                             SMEM_BYTES);
        attr_set = true;
    }

    k_init<<<72, 256>>>(u, mu, wts);
    dim3 grid((IMW + TILE - 1) / TILE, (IMH + TILE - 1) / TILE, BATCH);
    k_main<<<grid, NTHR, SMEM_BYTES>>>(u, f, filt, lam, out);
}

// round 5
// speedup vs baseline: 1.3692x; 1.3692x over previous
#include <cuda_runtime.h>

// Problem constants
#define BATCH 8
#define IMH 180
#define IMW 180
#define NF 24
#define NB 31
#define NPIX (IMH * IMW)          // 32400
#define NTOT (BATCH * NPIX)       // 259200
#define N4   (NTOT / 4)           // 64800

#define TILE 32
#define UT 40                      // u tile (TILE + 2*4)
#define PT 36                      // phi tile (TILE + 2*2)

// LUT for phi(x) = sum_j w_j exp(-50 (x-mu_j)^2), x in [XMIN, XMAX]
#define NCELL 2048
#define XMIN (-2.0f)
#define XMAX (2.0f)
#define LUT_H ((XMAX - XMIN) / (float)NCELL)
#define LUT_INVH ((float)NCELL / (XMAX - XMIN))

#define NTHR 384                   // 3 filter-groups of 128 threads
#define NFG  8                     // filters per group

__device__ float  g_partials[256];
__device__ float2 g_lut[NCELL];

// ---------------------------------------------------------------------------
// k_init: blocks [0,8) build the 2048-cell LUT; blocks [8,264) compute
// weighted partial sums for M: sum(u_sigma)*9 = sum_p u[p]*cnt(p).
// One float4 per thread -> single pass.
// ---------------------------------------------------------------------------
__global__ void k_init(const float* __restrict__ u,
                       const float* __restrict__ mu,
                       const float* __restrict__ wts) {
    const int tid = threadIdx.x;
    if (blockIdx.x < 8) {
        int i = blockIdx.x * 256 + tid;        // 0..2047
        float x0 = XMIN + (float)i * LUT_H;
        float x1 = x0 + LUT_H;
        float p0 = 0.f, p1 = 0.f;
        #pragma unroll 1
        for (int j = 0; j < NB; j++) {
            float m = mu[j], w = wts[j];
            float d0 = x0 - m, d1 = x1 - m;
            p0 += w * expf(-50.f * d0 * d0);
            p1 += w * expf(-50.f * d1 * d1);
        }
        g_lut[i] = make_float2(p0, p1 - p0);
    } else {
        __shared__ float sm[256];
        const int pb = blockIdx.x - 8;         // 0..255
        const int i = pb * 256 + tid;
        float s = 0.f;
        if (i < N4) {
            int idx4 = i * 4;
            int p = idx4 % NPIX;
            int y = p / IMW;
            int x0 = p - y * IMW;
            float wy = 3.f - (y == 0 ? 1.f : 0.f) - (y == IMH - 1 ? 1.f : 0.f);
            float4 v = ((const float4*)u)[i];
            float w0 = (x0 == 0) ? 2.f : 3.f;
            float w3 = (x0 == IMW - 4) ? 2.f : 3.f;
            s = wy * (v.x * w0 + v.y * 3.f + v.z * 3.f + v.w * w3);
        }
        sm[tid] = s;
        __syncthreads();
        for (int o = 128; o > 0; o >>= 1) {
            if (tid < o) sm[tid] += sm[tid + o];
            __syncthreads();
        }
        if (tid == 0) g_partials[pb] = sm[0];
    }
}

// ---------------------------------------------------------------------------
// k_main: fused TNRD stage per 32x32 tile; 3 filter-groups of 128 threads.
// Per group, per filter: forward(3x4 strips) -> bar -> adjoint(2x4 strips) -> bar.
// Same F[25] registers serve both phases (no smem tap reads in adjoint).
// Dynamic smem layout (bytes):
//   [0, 16384)       sLUT  : 2048 x float2
//   [16384, 22784)   sU    : 40x40
//   [22784, 27968)   sUS   : 36x36 (u_sigma/M, zeroed outside image)
//   [27968, 43520)   sPhi  : 3 buffers of 36x36 (one per group)
//   [43520, 45920)   sF    : 24x25
// ---------------------------------------------------------------------------
#define OFF_LUT 0
#define OFF_U   16384
#define OFF_US  22784
#define OFF_PHI 27968
#define OFF_F   43520
#define PHI_STRIDE 5184
#define SMEM_BYTES 45920

__global__ __launch_bounds__(NTHR, 2) void k_main(
    const float* __restrict__ u,
    const float* __restrict__ f,
    const float* __restrict__ filt,
    const float* __restrict__ lam,
    float* __restrict__ out)
{
    extern __shared__ char smem[];
    float2* sLUT = (float2*)(smem + OFF_LUT);
    float*  sU   = (float*)(smem + OFF_U);
    float*  sUS  = (float*)(smem + OFF_US);
    float*  sF   = (float*)(smem + OFF_F);
    __shared__ float red[256];

    const int b   = blockIdx.z;
    const int oy0 = blockIdx.y * TILE;
    const int ox0 = blockIdx.x * TILE;
    const int tid = threadIdx.x;
    const int g   = tid >> 7;          // filter-group 0/1/2
    const int gt  = tid & 127;         // lane within group

    const float* ub = u + b * NPIX;
    const float* fb = f + b * NPIX;
    float* ob = out + b * NPIX;

    float* sPhiG = (float*)(smem + OFF_PHI + g * PHI_STRIDE);

    // ---- cooperative loads ----
    if (tid < 256) red[tid] = g_partials[tid];
    {
        const float4* lg = (const float4*)g_lut;
        float4* ls = (float4*)sLUT;
        for (int i = tid; i < NCELL / 2; i += NTHR)   // 1024 float4
            ls[i] = lg[i];
    }
    for (int i = tid; i < NF * 25; i += NTHR) sF[i] = filt[i];
    for (int i = tid; i < UT * UT; i += NTHR) {
        int r = i / UT, c = i - r * UT;
        int gy = oy0 - 4 + r, gx = ox0 - 4 + c;
        float v = 0.f;
        if ((unsigned)gy < IMH && (unsigned)gx < IMW) v = ub[gy * IMW + gx];
        sU[i] = v;
    }
    __syncthreads();

    // ---- reduce 256 partials -> invM (deterministic tree) ----
    for (int o = 128; o > 0; o >>= 1) {
        if (tid < o) red[tid] += red[tid + o];
        __syncthreads();
    }
    const float invM = 1.f / (red[0] / (9.f * (float)NTOT) + 0.001f);

    // ---- u_sigma/M on phi tile; zero outside image ----
    for (int i = tid; i < PT * PT; i += NTHR) {
        int r = i / PT, c = i - r * PT;
        int gy = oy0 - 2 + r, gx = ox0 - 2 + c;
        float v = 0.f;
        if ((unsigned)gy < IMH && (unsigned)gx < IMW) {
            float s0 = sU[(r + 1) * UT + c + 1] + sU[(r + 1) * UT + c + 2] + sU[(r + 1) * UT + c + 3];
            float s1 = sU[(r + 2) * UT + c + 1] + sU[(r + 2) * UT + c + 2] + sU[(r + 2) * UT + c + 3];
            float s2 = sU[(r + 3) * UT + c + 1] + sU[(r + 3) * UT + c + 2] + sU[(r + 3) * UT + c + 3];
            v = (s0 + s1 + s2) * (1.f / 9.f) * invM;
        }
        sUS[i] = v;
    }
    __syncthreads();

    // ---- per-thread fixed strips ----
    // forward: 108 tasks of 3 rows x 4 cols over the 36x36 phi tile
    const int ffr0 = (gt / 9) * 3;
    const int ffc0 = (gt % 9) * 4;
    const bool fwd_on = (gt < 108);
    // adjoint: 128 tasks of 2 rows x 4 cols over the 32x32 output tile
    const int qr0 = (gt >> 3) * 2;
    const int qc0 = (gt & 7) * 4;

    float acc[8];
    #pragma unroll
    for (int k = 0; k < 8; k++) acc[k] = 0.f;

    const int fbase = g * NFG;

    #define GBAR() asm volatile("bar.sync %0, %1;" :: "r"(g + 1), "r"(128) : "memory")

    #pragma unroll 1
    for (int kf = 0; kf < NFG; kf++) {
        // filter taps into registers (broadcast loads), shared by both phases
        float F[25];
        #pragma unroll
        for (int j = 0; j < 25; j++) F[j] = sF[(fbase + kf) * 25 + j];

        // ---- forward: conv 5x5 + LUT phi + scale -> sPhiG ----
        if (fwd_on) {
            float a[12];
            #pragma unroll
            for (int k = 0; k < 12; k++) a[k] = 0.f;
            #pragma unroll
            for (int dy = 0; dy < 7; dy++) {
                const float4* rp = (const float4*)&sU[(ffr0 + dy) * UT + ffc0];
                float4 A = rp[0], B = rp[1];
                float w[8] = {A.x, A.y, A.z, A.w, B.x, B.y, B.z, B.w};
                #pragma unroll
                for (int r = 0; r < 3; r++) {
                    if (dy - r >= 0 && dy - r <= 4) {
                        const int ky = dy - r;
                        #pragma unroll
                        for (int kx = 0; kx < 5; kx++) {
                            #pragma unroll
                            for (int k = 0; k < 4; k++)
                                a[r * 4 + k] = fmaf(w[kx + k], F[ky * 5 + kx], a[r * 4 + k]);
                        }
                    }
                }
            }
            #pragma unroll
            for (int r = 0; r < 3; r++) {
                float4 usv = *(const float4*)&sUS[(ffr0 + r) * PT + ffc0];
                float us[4] = {usv.x, usv.y, usv.z, usv.w};
                float res[4];
                #pragma unroll
                for (int k = 0; k < 4; k++) {
                    float xc = fminf(fmaxf(a[r * 4 + k], XMIN), XMAX);
                    float tt = (xc - XMIN) * LUT_INVH;
                    int ii = (int)tt;
                    ii = min(ii, NCELL - 1);
                    float frac = tt - (float)ii;
                    float2 cell = sLUT[ii];
                    res[k] = us[k] * fmaf(cell.y, frac, cell.x);
                }
                *(float4*)&sPhiG[(ffr0 + r) * PT + ffc0] =
                    make_float4(res[0], res[1], res[2], res[3]);
            }
        }
        GBAR();

        // ---- adjoint: conv with flipped taps, same F registers ----
        {
            float a[8];
            #pragma unroll
            for (int k = 0; k < 8; k++) a[k] = 0.f;
            #pragma unroll
            for (int dy = 0; dy < 6; dy++) {
                const float4* rp = (const float4*)&sPhiG[(qr0 + dy) * PT + qc0];
                float4 A = rp[0], B = rp[1];
                float w[8] = {A.x, A.y, A.z, A.w, B.x, B.y, B.z, B.w};
                #pragma unroll
                for (int r = 0; r < 2; r++) {
                    if (dy - r >= 0 && dy - r <= 4) {
                        const int ky = dy - r;
                        #pragma unroll
                        for (int kx = 0; kx < 5; kx++) {
                            #pragma unroll
                            for (int k = 0; k < 4; k++)
                                a[r * 4 + k] = fmaf(w[kx + k], F[(4 - ky) * 5 + (4 - kx)], a[r * 4 + k]);
                        }
                    }
                }
            }
            #pragma unroll
            for (int k = 0; k < 8; k++) acc[k] += a[k];
        }
        GBAR();
    }
    #undef GBAR

    // ---- combine group accumulators (groups 1,2 -> smem; group 0 sums) ----
    __syncthreads();                 // all groups done with their phi buffers
    if (g > 0) {
        float4* buf = (float4*)(smem + OFF_PHI + g * PHI_STRIDE);
        buf[gt * 2 + 0] = make_float4(acc[0], acc[1], acc[2], acc[3]);
        buf[gt * 2 + 1] = make_float4(acc[4], acc[5], acc[6], acc[7]);
    }
    __syncthreads();

    // ---- epilogue: reaction + clip (group 0) ----
    if (g == 0) {
        const float4* buf1 = (const float4*)(smem + OFF_PHI + 1 * PHI_STRIDE);
        const float4* buf2 = (const float4*)(smem + OFF_PHI + 2 * PHI_STRIDE);
        float4 c10 = buf1[gt * 2 + 0], c11 = buf1[gt * 2 + 1];
        float4 c20 = buf2[gt * 2 + 0], c21 = buf2[gt * 2 + 1];
        acc[0] += c10.x + c20.x; acc[1] += c10.y + c20.y;
        acc[2] += c10.z + c20.z; acc[3] += c10.w + c20.w;
        acc[4] += c11.x + c21.x; acc[5] += c11.y + c21.y;
        acc[6] += c11.z + c21.z; acc[7] += c11.w + c21.w;

        const float lambda = lam[0];
        #pragma unroll
        for (int r = 0; r < 2; r++) {
            const int gy = oy0 + qr0 + r;
            if (gy < IMH) {
                float4 uv4 = *(const float4*)&sU[(qr0 + r + 4) * UT + qc0 + 4];
                float uvs[4] = {uv4.x, uv4.y, uv4.z, uv4.w};
                #pragma unroll
                for (int k = 0; k < 4; k++) {
                    int gx = ox0 + qc0 + k;
                    if (gx < IMW) {
                        float uv = uvs[k];
                        float fv = fb[gy * IMW + gx];
                        float reac = lambda * (uv - fv) / (uv * uv + 1e-3f);
                        float o = uv - acc[r * 4 + k] - reac;
                        o = fminf(fmaxf(o, 0.f), 1.f);
                        ob[gy * IMW + gx] = o;
                    }
                }
            }
        }
    }
}

// ---------------------------------------------------------------------------
// Launch
// ---------------------------------------------------------------------------
extern "C" void kernel_launch(void* const* d_in, const int* in_sizes, int n_in,
                              void* d_out, int out_size) {
    const float* u    = (const float*)d_in[0];
    const float* f    = (const float*)d_in[1];
    const float* filt = (const float*)d_in[2];
    const float* lam  = (const float*)d_in[3];
    const float* mu   = (const float*)d_in[4];
    const float* wts  = (const float*)d_in[5];
    float* out = (float*)d_out;

    k_init<<<264, 256>>>(u, mu, wts);
    dim3 grid((IMW + TILE - 1) / TILE, (IMH + TILE - 1) / TILE, BATCH);
    k_main<<<grid, NTHR, SMEM_BYTES>>>(u, f, filt, lam, out);
}